// round 7
// baseline (speedup 1.0000x reference)
#include <cuda_runtime.h>
#include <math.h>

// Problem constants
#define Bq  4
#define Nn  8192
#define Cc  256
#define Ee  262144
#define NC  (Nn * Cc)          // 2,097,152
#define Mtot (Bq * Nn)         // 32768 rows in the GEMM

// ---------------- scratch (static device globals — no allocation) -----------
__device__ int   g_deg[Nn];
__device__ int   g_cur[Nn];
__device__ int   g_off[Nn + 1];
__device__ float g_invdeg[Nn];
__device__ int   g_col[Ee];
__device__ float g_agg[Bq * NC];   // 32 MB aggregated features
__device__ int   g_is64;           // edge_index element width flag

// ---------------- 0. detect int64-vs-int32 edge buffer ----------------------
// int64 layout with values < 8192: every odd 32-bit word is 0.
// int32 layout: odd words are uniform indices in [0,8192) — never all zero.
__global__ void detect_k(const unsigned* __restrict__ w) {
    if (threadIdx.x == 0) {
        int nz = 0;
        for (int i = 0; i < 1024; i++) nz += (w[2 * i + 1] != 0u);
        g_is64 = (nz == 0) ? 1 : 0;
    }
}

__device__ __forceinline__ int load_idx(const unsigned* w, int pos) {
    // pos in [0, 2*Ee): logical int index into edge_index
    int v = g_is64 ? (int)w[2 * pos] : (int)w[pos];
    return v & (Nn - 1);   // mask — memory-safe under any misinterpretation
}

// ---------------- 1. zero counters ------------------------------------------
__global__ void zero_k() {
    int i = blockIdx.x * blockDim.x + threadIdx.x;
    if (i < Nn) { g_deg[i] = 0; g_cur[i] = 0; }
}

// ---------------- 2. degree counting ----------------------------------------
__global__ void count_k(const unsigned* __restrict__ w) {
    int e = blockIdx.x * blockDim.x + threadIdx.x;
    if (e < Ee) atomicAdd(&g_deg[load_idx(w, e)], 1);   // src row
}

// ---------------- 3. exclusive scan (one block, 1024 thr * 8 items) ---------
__global__ void scan_k() {
    __shared__ int s[1024];
    int tid = threadIdx.x;
    int v[8]; int sum = 0;
#pragma unroll
    for (int k = 0; k < 8; k++) { v[k] = g_deg[tid * 8 + k]; sum += v[k]; }
    s[tid] = sum;
    __syncthreads();
    for (int ofs = 1; ofs < 1024; ofs <<= 1) {
        int t = (tid >= ofs) ? s[tid - ofs] : 0;
        __syncthreads();
        s[tid] += t;
        __syncthreads();
    }
    int excl = (tid == 0) ? 0 : s[tid - 1];
#pragma unroll
    for (int k = 0; k < 8; k++) {
        int i = tid * 8 + k;
        g_off[i]    = excl;
        g_invdeg[i] = 1.0f / (float)(v[k] + 1);   // +1 self loop
        excl += v[k];
    }
    if (tid == 1023) g_off[Nn] = excl;
}

// ---------------- 4. CSR fill ------------------------------------------------
__global__ void fill_k(const unsigned* __restrict__ w) {
    int e = blockIdx.x * blockDim.x + threadIdx.x;
    if (e < Ee) {
        int src = load_idx(w, e);
        int dst = load_idx(w, Ee + e);
        int p = atomicAdd(&g_cur[src], 1);
        g_col[g_off[src] + p] = dst;
    }
}

// ---------------- 5. neighbor aggregation -----------------------------------
// One block per node i. 256 threads = (batch b in [0,4)) x (64 float4 channel
// groups). Each neighbor costs one coalesced LDG.128 per thread.
__global__ __launch_bounds__(256) void agg_k(const float* __restrict__ x) {
    int i   = blockIdx.x;
    int tid = threadIdx.x;
    int b   = tid >> 6;            // 0..3
    int cg  = (tid & 63) << 2;     // channel*4
    const float* xb = x + (size_t)b * NC;

    float4 acc = *(const float4*)(xb + (size_t)i * Cc + cg);   // self loop
    int s = g_off[i], e = g_off[i + 1];

    __shared__ int nb[256];
    for (int base = s; base < e; base += 256) {
        int cnt = min(256, e - base);
        __syncthreads();
        if (tid < cnt) nb[tid] = g_col[base + tid];
        __syncthreads();
#pragma unroll 4
        for (int k = 0; k < cnt; k++) {
            const float4 v = *(const float4*)(xb + (size_t)nb[k] * Cc + cg);
            acc.x += v.x; acc.y += v.y; acc.z += v.z; acc.w += v.w;
        }
    }
    float wgt = g_invdeg[i];
    float4 r = make_float4(acc.x * wgt, acc.y * wgt, acc.z * wgt, acc.w * wgt);
    *(float4*)(g_agg + (size_t)b * NC + (size_t)i * Cc + cg) = r;
}

// ---------------- 6. fused dual GEMM + bias + exact GELU ---------------------
// out[m,n] = gelu( x[m,:]@Ws[:,n] + agg[m,:]@Wn[:,n] + bs[n]+bn[n] )
// Single logical K=512 GEMM: k-tiles 0..15 -> (x, Ws); 16..31 -> (agg, Wn).
#define BM 64
#define BN 64
#define BK 16
__global__ __launch_bounds__(256) void gemm_k(
    const float* __restrict__ x,
    const float* __restrict__ Ws, const float* __restrict__ bs,
    const float* __restrict__ Wn, const float* __restrict__ bn,
    float* __restrict__ out)
{
    __shared__ __align__(16) float As[BK][BM];
    __shared__ __align__(16) float Bs[BK][BN];

    int m0  = blockIdx.x * BM;
    int n0  = blockIdx.y * BN;
    int tid = threadIdx.x;
    int tx  = tid & 15;
    int ty  = tid >> 4;

    int arow = tid >> 2, ak = (tid & 3) << 2;   // A: row + k4 offset
    int bkr  = tid >> 4, bn4 = (tid & 15) << 2; // B: k-row + n4 offset

    float acc[4][4] = {};

    for (int kt = 0; kt < 32; kt++) {
        const float* Ab = (kt < 16) ? x  : g_agg;
        const float* Wb = (kt < 16) ? Ws : Wn;
        int kk0 = (kt & 15) * BK;

        float4 av = *(const float4*)(Ab + (size_t)(m0 + arow) * Cc + kk0 + ak);
        As[ak + 0][arow] = av.x;
        As[ak + 1][arow] = av.y;
        As[ak + 2][arow] = av.z;
        As[ak + 3][arow] = av.w;

        float4 bv = *(const float4*)(Wb + (size_t)(kk0 + bkr) * Cc + n0 + bn4);
        *(float4*)&Bs[bkr][bn4] = bv;
        __syncthreads();

#pragma unroll
        for (int kk = 0; kk < BK; kk++) {
            float4 a4 = *(const float4*)&As[kk][ty << 2];
            float4 b4 = *(const float4*)&Bs[kk][tx << 2];
            float a[4] = {a4.x, a4.y, a4.z, a4.w};
            float b[4] = {b4.x, b4.y, b4.z, b4.w};
#pragma unroll
            for (int i = 0; i < 4; i++)
#pragma unroll
                for (int j = 0; j < 4; j++)
                    acc[i][j] += a[i] * b[j];
        }
        __syncthreads();
    }

#pragma unroll
    for (int j = 0; j < 4; j++) {
        int n = n0 + (tx << 2) + j;
        float bias = bs[n] + bn[n];
#pragma unroll
        for (int i = 0; i < 4; i++) {
            int m = m0 + (ty << 2) + i;
            float h = acc[i][j] + bias;
            out[(size_t)m * Cc + n] = 0.5f * h * (1.0f + erff(h * 0.70710678118654752f));
        }
    }
}

// ---------------- launch -----------------------------------------------------
extern "C" void kernel_launch(void* const* d_in, const int* in_sizes, int n_in,
                              void* d_out, int out_size)
{
    // Resolve inputs by element count — no ordering/dtype assumptions.
    const float* x = 0; const unsigned* ei = 0;
    const float* Ws = 0; const float* bs = 0;
    const float* Wn = 0; const float* bn = 0;
    for (int i = 0; i < n_in; i++) {
        int sz = in_sizes[i];
        if (sz == Bq * NC)                      x  = (const float*)d_in[i];
        else if (sz == 2 * Ee || sz == 4 * Ee)  ei = (const unsigned*)d_in[i];
        else if (sz == Cc * Cc)                 { if (!Ws) Ws = (const float*)d_in[i]; else Wn = (const float*)d_in[i]; }
        else if (sz == Cc)                      { if (!bs) bs = (const float*)d_in[i]; else bn = (const float*)d_in[i]; }
    }
    float* out = (float*)d_out;

    detect_k<<<1, 32>>>(ei);
    zero_k  <<<(Nn + 255) / 256, 256>>>();
    count_k <<<Ee / 256, 256>>>(ei);
    scan_k  <<<1, 1024>>>();
    fill_k  <<<Ee / 256, 256>>>(ei);
    agg_k   <<<Nn, 256>>>(x);

    dim3 ggrid(Mtot / BM, Cc / BN);   // (512, 4)
    gemm_k  <<<ggrid, 256>>>(x, Ws, bs, Wn, bn, out);
}

// round 12
// speedup vs baseline: 1.8778x; 1.8778x over previous
#include <cuda_runtime.h>
#include <cuda_bf16.h>
#include <math.h>
#include <stdint.h>

// Problem constants
#define Bq  4
#define Nn  8192
#define Cc  256
#define Ee  262144
#define NC  (Nn * Cc)          // 2,097,152
#define Mtot (Bq * Nn)         // 32768 rows in the GEMM

// ---------------------------------------------------------------------------
// helpers (plain sm_103-safe ISA only: cp.async / ldmatrix / mma.sync)
// ---------------------------------------------------------------------------
__device__ __forceinline__ uint32_t smem_u32(const void* p) {
    uint32_t a;
    asm("{ .reg .u64 t; cvta.to.shared.u64 t, %1; cvt.u32.u64 %0, t; }"
        : "=r"(a) : "l"(p));
    return a;
}
#define CP_ASYNC16(dst, src) \
    asm volatile("cp.async.cg.shared.global [%0], [%1], 16;" :: "r"(dst), "l"(src))
#define CP_COMMIT() asm volatile("cp.async.commit_group;" ::: "memory")
#define CP_WAIT1()  asm volatile("cp.async.wait_group 1;" ::: "memory")
#define CP_WAIT0()  asm volatile("cp.async.wait_group 0;" ::: "memory")
#define LDSM_X4(r0, r1, r2, r3, a) \
    asm volatile("ldmatrix.sync.aligned.m8n8.x4.shared.b16 {%0,%1,%2,%3}, [%4];" \
                 : "=r"(r0), "=r"(r1), "=r"(r2), "=r"(r3) : "r"(a))
#define MMA_BF16(c, a, b0, b1) \
    asm volatile("mma.sync.aligned.m16n8k16.row.col.f32.bf16.bf16.f32 " \
                 "{%0,%1,%2,%3}, {%4,%5,%6,%7}, {%8,%9}, {%0,%1,%2,%3};" \
                 : "+f"((c)[0]), "+f"((c)[1]), "+f"((c)[2]), "+f"((c)[3]) \
                 : "r"((a)[0]), "r"((a)[1]), "r"((a)[2]), "r"((a)[3]), \
                   "r"(b0), "r"(b1))

__device__ __forceinline__ float gelu_f(float h) {
    return 0.5f * h * (1.0f + erff(h * 0.70710678118654752f));
}

// ---------------- scratch (static device globals — no allocation) -----------
__device__ int   g_deg[Nn];
__device__ int   g_cur[Nn];
__device__ int   g_off[Nn + 1];
__device__ float g_invdeg[Nn];
__device__ int   g_col[Ee];
__device__ int   g_is64;
__device__ __align__(16) __nv_bfloat16 g_xh[Mtot * Cc];   // x hi
__device__ __align__(16) __nv_bfloat16 g_xl[Mtot * Cc];   // x lo
__device__ __align__(16) __nv_bfloat16 g_ah[Mtot * Cc];   // agg hi
__device__ __align__(16) __nv_bfloat16 g_al[Mtot * Cc];   // agg lo
__device__ __align__(16) __nv_bfloat16 g_wsh[Cc * Cc];    // W_self^T hi (n-major, k contig)
__device__ __align__(16) __nv_bfloat16 g_wsl[Cc * Cc];
__device__ __align__(16) __nv_bfloat16 g_wnh[Cc * Cc];    // W_neigh^T hi
__device__ __align__(16) __nv_bfloat16 g_wnl[Cc * Cc];

// ---------------- 0. detect int64-vs-int32 edge buffer ----------------------
__global__ void detect_k(const unsigned* __restrict__ w) {
    int nz = (w[2 * threadIdx.x + 1] != 0u);
    int total = __syncthreads_count(nz);
    if (threadIdx.x == 0) g_is64 = (total == 0) ? 1 : 0;
}
__device__ __forceinline__ int load_idx(const unsigned* w, int pos) {
    int v = g_is64 ? (int)w[2 * pos] : (int)w[pos];
    return v & (Nn - 1);
}

// ---------------- 1. zero counters ------------------------------------------
__global__ void zero_k() {
    int i = blockIdx.x * blockDim.x + threadIdx.x;
    if (i < Nn) { g_deg[i] = 0; g_cur[i] = 0; }
}

// ---------------- 2. degree counting ----------------------------------------
__global__ void count_k(const unsigned* __restrict__ w) {
    int e = blockIdx.x * blockDim.x + threadIdx.x;
    if (e < Ee) atomicAdd(&g_deg[load_idx(w, e)], 1);
}

// ---------------- 3. exclusive scan (warp-shuffle, 256 thr * 32 items) ------
__global__ void scan_k() {
    __shared__ int wsum[8], wexc[8];
    int tid = threadIdx.x;
    int v[32]; int s = 0;
#pragma unroll
    for (int k = 0; k < 32; k++) { v[k] = g_deg[tid * 32 + k]; s += v[k]; }
    int incl = s;
#pragma unroll
    for (int d = 1; d < 32; d <<= 1) {
        int t = __shfl_up_sync(0xFFFFFFFFu, incl, d);
        if ((tid & 31) >= d) incl += t;
    }
    if ((tid & 31) == 31) wsum[tid >> 5] = incl;
    __syncthreads();
    if (tid < 8) {
        int e = 0;
        for (int q = 0; q < tid; q++) e += wsum[q];
        wexc[tid] = e;
    }
    __syncthreads();
    int excl = wexc[tid >> 5] + incl - s;
#pragma unroll
    for (int k = 0; k < 32; k++) {
        int i = tid * 32 + k;
        g_off[i]    = excl;
        g_invdeg[i] = 1.0f / (float)(v[k] + 1);
        excl += v[k];
    }
    if (tid == 255) g_off[Nn] = excl;
}

// ---------------- 4. CSR fill ------------------------------------------------
__global__ void fill_k(const unsigned* __restrict__ w) {
    int e = blockIdx.x * blockDim.x + threadIdx.x;
    if (e < Ee) {
        int src = load_idx(w, e);
        int dst = load_idx(w, Ee + e);
        int p = atomicAdd(&g_cur[src], 1);
        g_col[g_off[src] + p] = dst;
    }
}

// ---------------- 5a. x split into bf16 hi/lo --------------------------------
__global__ __launch_bounds__(256) void xsplit_k(const float* __restrict__ x) {
    size_t t = (size_t)blockIdx.x * blockDim.x + threadIdx.x;  // float4 index
    float4 v = *(const float4*)(x + t * 4);
    float f[4] = {v.x, v.y, v.z, v.w};
    ushort4 hi, lo;
    unsigned short* hp = &hi.x; unsigned short* lp = &lo.x;
#pragma unroll
    for (int q = 0; q < 4; q++) {
        __nv_bfloat16 h = __float2bfloat16(f[q]);
        hp[q] = __bfloat16_as_ushort(h);
        lp[q] = __bfloat16_as_ushort(__float2bfloat16(f[q] - __bfloat162float(h)));
    }
    *(ushort4*)(g_xh + t * 4) = hi;
    *(ushort4*)(g_xl + t * 4) = lo;
}

// ---------------- 5b. weight transpose + split --------------------------------
__global__ void wsplit_k(const float* __restrict__ Ws, const float* __restrict__ Wn) {
    int n = blockIdx.x, k = threadIdx.x;
    float a = Ws[k * Cc + n];
    __nv_bfloat16 h = __float2bfloat16(a);
    g_wsh[n * Cc + k] = h;
    g_wsl[n * Cc + k] = __float2bfloat16(a - __bfloat162float(h));
    float b = Wn[k * Cc + n];
    __nv_bfloat16 h2 = __float2bfloat16(b);
    g_wnh[n * Cc + k] = h2;
    g_wnl[n * Cc + k] = __float2bfloat16(b - __bfloat162float(h2));
}

// ---------------- 5c. neighbor aggregation (writes bf16 hi/lo) ---------------
__global__ __launch_bounds__(256) void agg_k(const float* __restrict__ x) {
    int i   = blockIdx.x;
    int tid = threadIdx.x;
    int b   = tid >> 6;
    int cg  = (tid & 63) << 2;
    const float* xb = x + (size_t)b * NC;

    float4 acc = *(const float4*)(xb + (size_t)i * Cc + cg);   // self loop
    int s = g_off[i], e = g_off[i + 1];

    __shared__ int nb[256];
    for (int base = s; base < e; base += 256) {
        int cnt = min(256, e - base);
        __syncthreads();
        if (tid < cnt) nb[tid] = g_col[base + tid];
        __syncthreads();
#pragma unroll 4
        for (int k = 0; k < cnt; k++) {
            const float4 v = *(const float4*)(xb + (size_t)nb[k] * Cc + cg);
            acc.x += v.x; acc.y += v.y; acc.z += v.z; acc.w += v.w;
        }
    }
    float wgt = g_invdeg[i];
    float f[4] = {acc.x * wgt, acc.y * wgt, acc.z * wgt, acc.w * wgt};
    ushort4 hi, lo;
    unsigned short* hp = &hi.x; unsigned short* lp = &lo.x;
#pragma unroll
    for (int q = 0; q < 4; q++) {
        __nv_bfloat16 h = __float2bfloat16(f[q]);
        hp[q] = __bfloat16_as_ushort(h);
        lp[q] = __bfloat16_as_ushort(__float2bfloat16(f[q] - __bfloat162float(h)));
    }
    size_t o = (size_t)b * NC + (size_t)i * Cc + cg;
    *(ushort4*)(g_ah + o) = hi;
    *(ushort4*)(g_al + o) = lo;
}

// ---------------- 6. mma.sync split-GEMM + bias + exact GELU -----------------
// out[m,n] = gelu( sum_{6 terms} A_t[m,:] @ B_t[n,:]^T + bias[n] )
// CTA: 128(M) x 128(N), 8 warps (2x4), warp tile 64x32. K-chunk 64 bf16,
// 24 chunks (6 terms x 4). Double-buffered cp.async. SMEM rows padded to
// 144B (72 bf16) -> conflict-free ldmatrix.
#define ROWB   144              // bytes per padded smem row (64 bf16 + 8 pad)
#define TILE_B (128 * ROWB)     // 18432 B per A or B stage
#define STG_B  (2 * TILE_B)     // A+B per stage
#define GSMEM  (2 * STG_B)      // 73728 B total
__global__ __launch_bounds__(256, 2) void gemm_mma(
    const float* __restrict__ bs, const float* __restrict__ bn,
    float* __restrict__ out)
{
    extern __shared__ __align__(128) char smem[];
    uint32_t sb = smem_u32(smem);
    int tid = threadIdx.x, lane = tid & 31, wid = tid >> 5;
    int m0 = blockIdx.x * 128, n0 = blockIdx.y * 128;
    int wm = (wid >> 2) * 64;   // warp m offset
    int wn = (wid & 3) * 32;    // warp n offset

    const __nv_bfloat16* Asrc[6] = {g_xh, g_xl, g_xh, g_ah, g_al, g_ah};
    const __nv_bfloat16* Bsrc[6] = {g_wsh, g_wsh, g_wsl, g_wnh, g_wnh, g_wnl};

    float acc[4][4][4] = {};

    // ---- loader: tile (it) -> buffer (buf). 128 rows x 64 bf16 each for A,B.
    auto load_tile = [&](int it, int buf) {
        int term = it >> 2, kc = (it & 3) * 64;
        const __nv_bfloat16* A = Asrc[term];
        const __nv_bfloat16* B = Bsrc[term];
        uint32_t ab = sb + buf * STG_B;
        uint32_t bb = ab + TILE_B;
#pragma unroll
        for (int c = 0; c < 4; c++) {
            int id = tid + 256 * c, row = id >> 3, ch = id & 7;
            CP_ASYNC16(ab + row * ROWB + ch * 16,
                       A + (size_t)(m0 + row) * Cc + kc + ch * 8);
            CP_ASYNC16(bb + row * ROWB + ch * 16,
                       B + (size_t)(n0 + row) * Cc + kc + ch * 8);
        }
        CP_COMMIT();
    };

    load_tile(0, 0);
    load_tile(1, 1);

    for (int it = 0; it < 24; it++) {
        int buf = it & 1;
        if (it < 22) CP_WAIT1(); else CP_WAIT0();
        __syncthreads();

        uint32_t ab = sb + buf * STG_B;
        uint32_t bb = ab + TILE_B;
        // ldmatrix lane addresses (A: rows=m, cols=k; B: rows=n, cols=k)
        uint32_t a_l = ab + (wm + (lane & 15)) * ROWB + (lane >> 4) * 16;
        uint32_t b_l = bb + (wn + (lane & 7) + ((lane >> 4) & 1) * 8) * ROWB
                          + ((lane >> 3) & 1) * 16;

#pragma unroll
        for (int s = 0; s < 4; s++) {            // 4 x k16 within the k64 chunk
            uint32_t ar[4][4];
#pragma unroll
            for (int i = 0; i < 4; i++)
                LDSM_X4(ar[i][0], ar[i][1], ar[i][2], ar[i][3],
                        a_l + i * 16 * ROWB + s * 32);
            uint32_t br[2][4];
#pragma unroll
            for (int j = 0; j < 2; j++)
                LDSM_X4(br[j][0], br[j][1], br[j][2], br[j][3],
                        b_l + j * 16 * ROWB + s * 32);
#pragma unroll
            for (int i = 0; i < 4; i++)
#pragma unroll
                for (int jn = 0; jn < 4; jn++)
                    MMA_BF16(acc[i][jn], ar[i],
                             br[jn >> 1][(jn & 1) * 2],
                             br[jn >> 1][(jn & 1) * 2 + 1]);
        }
        __syncthreads();
        if (it + 2 < 24) load_tile(it + 2, buf);
    }

    // ---- epilogue: bias + exact GELU, float2 stores
    int g = lane >> 2, tig = lane & 3;
#pragma unroll
    for (int jn = 0; jn < 4; jn++) {
        int n = n0 + wn + jn * 8 + tig * 2;
        float b0 = bs[n] + bn[n];
        float b1 = bs[n + 1] + bn[n + 1];
#pragma unroll
        for (int i = 0; i < 4; i++) {
            int m = m0 + wm + i * 16 + g;
            float2 v0 = make_float2(gelu_f(acc[i][jn][0] + b0),
                                    gelu_f(acc[i][jn][1] + b1));
            *(float2*)(out + (size_t)m * Cc + n) = v0;
            float2 v1 = make_float2(gelu_f(acc[i][jn][2] + b0),
                                    gelu_f(acc[i][jn][3] + b1));
            *(float2*)(out + (size_t)(m + 8) * Cc + n) = v1;
        }
    }
}

// ---------------- launch -----------------------------------------------------
extern "C" void kernel_launch(void* const* d_in, const int* in_sizes, int n_in,
                              void* d_out, int out_size)
{
    const float* x = 0; const unsigned* ei = 0;
    const float* Ws = 0; const float* bsv = 0;
    const float* Wn = 0; const float* bnv = 0;
    for (int i = 0; i < n_in; i++) {
        int sz = in_sizes[i];
        if (sz == Bq * NC)                      x  = (const float*)d_in[i];
        else if (sz == 2 * Ee || sz == 4 * Ee)  ei = (const unsigned*)d_in[i];
        else if (sz == Cc * Cc) { if (!Ws) Ws = (const float*)d_in[i]; else Wn = (const float*)d_in[i]; }
        else if (sz == Cc)      { if (!bsv) bsv = (const float*)d_in[i]; else bnv = (const float*)d_in[i]; }
    }
    float* out = (float*)d_out;

    static int smem_set = 0;
    if (!smem_set) {
        cudaFuncSetAttribute(gemm_mma, cudaFuncAttributeMaxDynamicSharedMemorySize, GSMEM);
        smem_set = 1;
    }

    detect_k <<<1, 1024>>>(ei);
    zero_k   <<<(Nn + 255) / 256, 256>>>();
    count_k  <<<Ee / 256, 256>>>(ei);
    scan_k   <<<1, 256>>>();
    fill_k   <<<Ee / 256, 256>>>(ei);
    xsplit_k <<<(Mtot * Cc / 4) / 256, 256>>>(x);
    wsplit_k <<<Cc, Cc>>>(Ws, Wn);
    agg_k    <<<Nn, 256>>>(x);

    dim3 ggrid(Mtot / 128, Cc / 128);   // (256, 2)
    gemm_mma <<<ggrid, 256, GSMEM>>>(bsv, bnv, out);
}